// round 2
// baseline (speedup 1.0000x reference)
#include <cuda_runtime.h>

#define SEQ   6272
#define QTILES 98

// Scratch (allocation-free: __device__ globals), all 16B-aligned for float4/cp.async
__device__ __align__(256) float g_theta[2 * SEQ * 128];
__device__ __align__(256) float g_phi  [2 * SEQ * 128];
__device__ __align__(256) float g_gx   [2 * SEQ * 128];
__device__ __align__(256) float g_y    [2 * SEQ * 128];

__device__ __forceinline__ unsigned smaddr(const void* p) {
    unsigned r;
    asm("{.reg .u64 t; cvta.to.shared.u64 t, %1; cvt.u32.u64 %0, t;}" : "=r"(r) : "l"(p));
    return r;
}

__device__ __forceinline__ void cp16(unsigned s, const void* g) {
    asm volatile("cp.async.cg.shared.global [%0], [%1], 16;" :: "r"(s), "l"(g) : "memory");
}

// ---------------------------------------------------------------------------
// Kernel 1: projections.  out[n][l][h] = sum_c w[h][c] * x[n][c][l] + b[h]
// One block = 64 L-positions x 128 channels for one (n, proj).
// smem: x tile [256][68] (c-major), w tile [128][260].
// ---------------------------------------------------------------------------
#define PROJ_SMEM ((256*68 + 128*260) * 4)

__global__ void __launch_bounds__(256, 1) proj_kernel(
    const float* __restrict__ x,
    const float* __restrict__ gw, const float* __restrict__ gb,
    const float* __restrict__ tw, const float* __restrict__ tb,
    const float* __restrict__ pw, const float* __restrict__ pb)
{
    extern __shared__ float sm[];
    float* xs = sm;            // [256][68]
    float* ws = sm + 256*68;   // [128][260]
    const int tid = threadIdx.x, tx = tid & 15, ty = tid >> 4;
    const int pidx = blockIdx.y, n = blockIdx.z;
    const int L0 = blockIdx.x * 64;

    const float* w = (pidx == 0) ? gw : (pidx == 1) ? tw : pw;
    const float* b = (pidx == 0) ? gb : (pidx == 1) ? tb : pb;
    float* out = ((pidx == 0) ? g_gx : (pidx == 1) ? g_theta : g_phi) + (size_t)n * SEQ * 128;

    // load x tile: 256 channels x 64 positions (coalesced float4 along l)
    const float* xg = x + (size_t)n * 256 * SEQ + L0;
    #pragma unroll
    for (int k = 0; k < 16; k++) {
        int chunk = tid + 256 * k;           // 4096 float4 chunks
        int c = chunk >> 4, l4 = chunk & 15;
        *(float4*)(xs + c*68 + l4*4) = *(const float4*)(xg + (size_t)c * SEQ + l4*4);
    }
    // load w: 128 x 256
    #pragma unroll
    for (int k = 0; k < 32; k++) {
        int chunk = tid + 256 * k;           // 8192 float4 chunks
        int h = chunk >> 6, c4 = chunk & 63;
        *(float4*)(ws + h*260 + c4*4) = *(const float4*)(w + h*256 + c4*4);
    }
    __syncthreads();

    // thread computes l = 4*ty + i (i<4), h = tx + 16*j (j<8)
    float acc[4][8];
    #pragma unroll
    for (int i = 0; i < 4; i++)
        #pragma unroll
        for (int j = 0; j < 8; j++) acc[i][j] = 0.f;

    #pragma unroll 2
    for (int c4 = 0; c4 < 64; c4++) {
        float4 xf[4];
        #pragma unroll
        for (int cc = 0; cc < 4; cc++)
            xf[cc] = *(const float4*)(xs + (c4*4 + cc)*68 + ty*4);
        float4 wf[8];
        #pragma unroll
        for (int j = 0; j < 8; j++)
            wf[j] = *(const float4*)(ws + (tx + 16*j)*260 + c4*4);
        #pragma unroll
        for (int cc = 0; cc < 4; cc++) {
            #pragma unroll
            for (int j = 0; j < 8; j++) {
                float wv = (cc == 0) ? wf[j].x : (cc == 1) ? wf[j].y : (cc == 2) ? wf[j].z : wf[j].w;
                acc[0][j] += xf[cc].x * wv;
                acc[1][j] += xf[cc].y * wv;
                acc[2][j] += xf[cc].z * wv;
                acc[3][j] += xf[cc].w * wv;
            }
        }
    }

    float bb[8];
    #pragma unroll
    for (int j = 0; j < 8; j++) bb[j] = b[tx + 16*j];
    #pragma unroll
    for (int i = 0; i < 4; i++) {
        float* o = out + (size_t)(L0 + 4*ty + i) * 128;
        #pragma unroll
        for (int j = 0; j < 8; j++) o[tx + 16*j] = acc[i][j] + bb[j];
    }
}

// ---------------------------------------------------------------------------
// Kernel 2: fused attention (flash style, fp32).
// Q=theta, K=phi, V=g, all (n, L, 128).  y[n][i][c] = softmax_j(Q_i.K_j) . V
// Block: 64 queries; loop over 98 key tiles of 64; online softmax.
// Threads 256 = 16x16; rows r = ty+16i (i<4); QK cols c = tx+16j (j<4);
// O cols c = 4tx + 64j (j<2).
// ---------------------------------------------------------------------------
#define ATTN_SMEM ((64*132 + 2*64*132 + 2*64*132 + 64*68) * 4)

__global__ void __launch_bounds__(256, 1) attn_kernel()
{
    extern __shared__ float sm[];
    float* Qs = sm;                    // [64][132]
    float* Ks = sm + 64*132;           // 2 x [64][132]
    float* Vs = Ks + 2*64*132;         // 2 x [64][132]
    float* Ps = Vs + 2*64*132;         // [64][68]
    const int tid = threadIdx.x, tx = tid & 15, ty = tid >> 4;
    const int n = blockIdx.y, q0 = blockIdx.x * 64;

    const float* Q = g_theta + (size_t)n * SEQ * 128;
    const float* K = g_phi   + (size_t)n * SEQ * 128;
    const float* V = g_gx    + (size_t)n * SEQ * 128;

    #pragma unroll
    for (int k = 0; k < 8; k++) {
        int chunk = tid + 256 * k;  int r = chunk >> 5, c4 = chunk & 31;
        cp16(smaddr(Qs + r*132 + c4*4), Q + (size_t)(q0 + r)*128 + c4*4);
    }
    #pragma unroll
    for (int k = 0; k < 8; k++) {
        int chunk = tid + 256 * k;  int r = chunk >> 5, c4 = chunk & 31;
        cp16(smaddr(Ks + r*132 + c4*4), K + (size_t)r*128 + c4*4);
        cp16(smaddr(Vs + r*132 + c4*4), V + (size_t)r*128 + c4*4);
    }
    asm volatile("cp.async.commit_group;" ::: "memory");

    float m[4], lsum[4], acc[4][8];
    #pragma unroll
    for (int i = 0; i < 4; i++) {
        m[i] = -1e30f; lsum[i] = 0.f;
        #pragma unroll
        for (int j = 0; j < 8; j++) acc[i][j] = 0.f;
    }

    for (int it = 0; it < QTILES; it++) {
        const int cur = it & 1;
        if (it + 1 < QTILES) {
            float* Kn = Ks + (1 - cur)*64*132;
            float* Vn = Vs + (1 - cur)*64*132;
            const float* Kg = K + (size_t)(it + 1)*64*128;
            const float* Vg = V + (size_t)(it + 1)*64*128;
            #pragma unroll
            for (int k = 0; k < 8; k++) {
                int chunk = tid + 256 * k;  int r = chunk >> 5, c4 = chunk & 31;
                cp16(smaddr(Kn + r*132 + c4*4), Kg + (size_t)r*128 + c4*4);
                cp16(smaddr(Vn + r*132 + c4*4), Vg + (size_t)r*128 + c4*4);
            }
            asm volatile("cp.async.commit_group;" ::: "memory");
            asm volatile("cp.async.wait_group 1;" ::: "memory");
        } else {
            asm volatile("cp.async.wait_group 0;" ::: "memory");
        }
        __syncthreads();

        const float* Kc = Ks + cur*64*132;
        const float* Vc = Vs + cur*64*132;

        // ---- S = Q K^T (64x64 tile) ----
        float s[4][4];
        #pragma unroll
        for (int i = 0; i < 4; i++)
            #pragma unroll
            for (int j = 0; j < 4; j++) s[i][j] = 0.f;

        #pragma unroll 4
        for (int k4 = 0; k4 < 32; k4++) {
            float4 qf[4], kf[4];
            #pragma unroll
            for (int i = 0; i < 4; i++) qf[i] = *(const float4*)(Qs + (ty + 16*i)*132 + k4*4);
            #pragma unroll
            for (int j = 0; j < 4; j++) kf[j] = *(const float4*)(Kc + (tx + 16*j)*132 + k4*4);
            #pragma unroll
            for (int i = 0; i < 4; i++)
                #pragma unroll
                for (int j = 0; j < 4; j++)
                    s[i][j] += qf[i].x*kf[j].x + qf[i].y*kf[j].y + qf[i].z*kf[j].z + qf[i].w*kf[j].w;
        }

        // ---- online softmax (row groups of 16 lanes share a row) ----
        #pragma unroll
        for (int i = 0; i < 4; i++) {
            float rmax = fmaxf(fmaxf(s[i][0], s[i][1]), fmaxf(s[i][2], s[i][3]));
            rmax = fmaxf(rmax, __shfl_xor_sync(0xffffffffu, rmax, 1));
            rmax = fmaxf(rmax, __shfl_xor_sync(0xffffffffu, rmax, 2));
            rmax = fmaxf(rmax, __shfl_xor_sync(0xffffffffu, rmax, 4));
            rmax = fmaxf(rmax, __shfl_xor_sync(0xffffffffu, rmax, 8));
            float mnew  = fmaxf(m[i], rmax);
            float alpha = __expf(m[i] - mnew);
            float p0 = __expf(s[i][0] - mnew);
            float p1 = __expf(s[i][1] - mnew);
            float p2 = __expf(s[i][2] - mnew);
            float p3 = __expf(s[i][3] - mnew);
            float rsum = p0 + p1 + p2 + p3;
            rsum += __shfl_xor_sync(0xffffffffu, rsum, 1);
            rsum += __shfl_xor_sync(0xffffffffu, rsum, 2);
            rsum += __shfl_xor_sync(0xffffffffu, rsum, 4);
            rsum += __shfl_xor_sync(0xffffffffu, rsum, 8);
            lsum[i] = lsum[i] * alpha + rsum;
            m[i] = mnew;
            #pragma unroll
            for (int jj = 0; jj < 8; jj++) acc[i][jj] *= alpha;
            float* pr = Ps + (ty + 16*i)*68;
            pr[tx]      = p0;
            pr[tx + 16] = p1;
            pr[tx + 32] = p2;
            pr[tx + 48] = p3;
        }
        __syncthreads();

        // ---- O += P V  (P: 64x64, V: 64x128) ----
        #pragma unroll 2
        for (int j4 = 0; j4 < 16; j4++) {
            float4 pf[4];
            #pragma unroll
            for (int i = 0; i < 4; i++)
                pf[i] = *(const float4*)(Ps + (ty + 16*i)*68 + j4*4);
            #pragma unroll
            for (int jj = 0; jj < 4; jj++) {
                const float* vr = Vc + (j4*4 + jj)*132;
                float4 v0 = *(const float4*)(vr + tx*4);
                float4 v1 = *(const float4*)(vr + tx*4 + 64);
                #pragma unroll
                for (int i = 0; i < 4; i++) {
                    float p = (jj == 0) ? pf[i].x : (jj == 1) ? pf[i].y : (jj == 2) ? pf[i].z : pf[i].w;
                    acc[i][0] += p * v0.x;  acc[i][1] += p * v0.y;
                    acc[i][2] += p * v0.z;  acc[i][3] += p * v0.w;
                    acc[i][4] += p * v1.x;  acc[i][5] += p * v1.y;
                    acc[i][6] += p * v1.z;  acc[i][7] += p * v1.w;
                }
            }
        }
        __syncthreads();
    }

    #pragma unroll
    for (int i = 0; i < 4; i++) {
        float inv = 1.0f / lsum[i];
        float* o = g_y + ((size_t)n * SEQ + q0 + ty + 16*i) * 128;
        float4 o0 = make_float4(acc[i][0]*inv, acc[i][1]*inv, acc[i][2]*inv, acc[i][3]*inv);
        float4 o1 = make_float4(acc[i][4]*inv, acc[i][5]*inv, acc[i][6]*inv, acc[i][7]*inv);
        *(float4*)(o + tx*4)      = o0;
        *(float4*)(o + tx*4 + 64) = o1;
    }
}

// ---------------------------------------------------------------------------
// Kernel 3: z[n][c][l] = sum_h wz[c][h] * y[n][l][h] + bz[c] + x[n][c][l]
// Block: 64 positions x all 256 output channels, one n.
// ---------------------------------------------------------------------------
#define OUT_SMEM ((64*132 + 256*132) * 4)

__global__ void __launch_bounds__(256, 1) out_kernel(
    const float* __restrict__ x,
    const float* __restrict__ wz, const float* __restrict__ bz,
    float* __restrict__ out)
{
    extern __shared__ float sm[];
    float* ys = sm;            // [64][132]
    float* ws = sm + 64*132;   // [256][132]
    const int tid = threadIdx.x, tx = tid & 15, ty = tid >> 4;
    const int n = blockIdx.y;
    const int L0 = blockIdx.x * 64;

    #pragma unroll
    for (int k = 0; k < 8; k++) {
        int chunk = tid + 256 * k;  int r = chunk >> 5, c4 = chunk & 31;
        *(float4*)(ys + r*132 + c4*4) =
            *(const float4*)(g_y + ((size_t)n * SEQ + L0 + r)*128 + c4*4);
    }
    #pragma unroll
    for (int k = 0; k < 32; k++) {
        int chunk = tid + 256 * k;  int c = chunk >> 5, h4 = chunk & 31;
        *(float4*)(ws + c*132 + h4*4) = *(const float4*)(wz + c*128 + h4*4);
    }
    __syncthreads();

    // thread: l = tx + 16*il (il<4), c = ty + 16*ic (ic<16)
    float acc[16][4];
    #pragma unroll
    for (int ic = 0; ic < 16; ic++)
        #pragma unroll
        for (int il = 0; il < 4; il++) acc[ic][il] = 0.f;

    for (int h4 = 0; h4 < 32; h4++) {
        float4 yf[4];
        #pragma unroll
        for (int il = 0; il < 4; il++)
            yf[il] = *(const float4*)(ys + (tx + 16*il)*132 + h4*4);
        float4 wf[16];
        #pragma unroll
        for (int ic = 0; ic < 16; ic++)
            wf[ic] = *(const float4*)(ws + (ty + 16*ic)*132 + h4*4);
        #pragma unroll
        for (int ic = 0; ic < 16; ic++)
            #pragma unroll
            for (int il = 0; il < 4; il++)
                acc[ic][il] += wf[ic].x*yf[il].x + wf[ic].y*yf[il].y
                             + wf[ic].z*yf[il].z + wf[ic].w*yf[il].w;
    }

    #pragma unroll
    for (int ic = 0; ic < 16; ic++) {
        int c = ty + 16*ic;
        float bb = bz[c];
        const float* xr = x   + ((size_t)n * 256 + c) * SEQ + L0;
        float*       zr = out + ((size_t)n * 256 + c) * SEQ + L0;
        #pragma unroll
        for (int il = 0; il < 4; il++) {
            int l = tx + 16*il;
            zr[l] = acc[ic][il] + bb + xr[l];
        }
    }
}

// ---------------------------------------------------------------------------
extern "C" void kernel_launch(void* const* d_in, const int* in_sizes, int n_in,
                              void* d_out, int out_size)
{
    (void)in_sizes; (void)n_in; (void)out_size;
    const float* x  = (const float*)d_in[0];
    const float* gw = (const float*)d_in[1];
    const float* gb = (const float*)d_in[2];
    const float* tw = (const float*)d_in[3];
    const float* tb = (const float*)d_in[4];
    const float* pw = (const float*)d_in[5];
    const float* pb = (const float*)d_in[6];
    const float* zw = (const float*)d_in[7];
    const float* zb = (const float*)d_in[8];
    float* out = (float*)d_out;

    cudaFuncSetAttribute(proj_kernel, cudaFuncAttributeMaxDynamicSharedMemorySize, PROJ_SMEM);
    cudaFuncSetAttribute(attn_kernel, cudaFuncAttributeMaxDynamicSharedMemorySize, ATTN_SMEM);
    cudaFuncSetAttribute(out_kernel,  cudaFuncAttributeMaxDynamicSharedMemorySize, OUT_SMEM);

    proj_kernel<<<dim3(QTILES, 3, 2), 256, PROJ_SMEM>>>(x, gw, gb, tw, tb, pw, pb);
    attn_kernel<<<dim3(QTILES, 2),    256, ATTN_SMEM>>>();
    out_kernel <<<dim3(QTILES, 2),    256, OUT_SMEM >>>(x, zw, zb, out);
}

// round 4
// speedup vs baseline: 3.1565x; 3.1565x over previous
#include <cuda_runtime.h>
#include <cuda_bf16.h>

#define SEQ    6272
#define QTILES 98      // 64-wide L tiles for proj/out kernels
#define NKT    98      // key tiles of 64 in attention
#define BM     128     // queries per CTA

// ---------------- device scratch (allocation-free) ----------------
__device__ __align__(256) __nv_bfloat16 g_qh[2*SEQ*128], g_ql[2*SEQ*128];   // theta, (n,l,h)
__device__ __align__(256) __nv_bfloat16 g_kh[2*SEQ*128], g_kl[2*SEQ*128];   // phi,   (n,l,h)
__device__ __align__(256) __nv_bfloat16 g_vh[2*128*SEQ], g_vl[2*128*SEQ];   // g, transposed (n,h,l)
__device__ __align__(256) float g_y[2*SEQ*128];                              // attn out (n,l,h) fp32

__device__ __forceinline__ unsigned smaddr(const void* p) {
    unsigned r;
    asm("{.reg .u64 t; cvta.to.shared.u64 t, %1; cvt.u32.u64 %0, t;}" : "=r"(r) : "l"(p));
    return r;
}
__device__ __forceinline__ void cp16(unsigned s, const void* g) {
    asm volatile("cp.async.cg.shared.global [%0], [%1], 16;" :: "r"(s), "l"(g) : "memory");
}
#define CP_COMMIT()  asm volatile("cp.async.commit_group;" ::: "memory")
#define CP_WAIT(N)   asm volatile("cp.async.wait_group %0;" :: "n"(N) : "memory")

__device__ __forceinline__ void ldsm4(unsigned* r, unsigned a) {
    asm volatile("ldmatrix.sync.aligned.m8n8.x4.shared.b16 {%0,%1,%2,%3}, [%4];"
        : "=r"(r[0]), "=r"(r[1]), "=r"(r[2]), "=r"(r[3]) : "r"(a));
}
__device__ __forceinline__ void mma_bf16(float* c, const unsigned* a, const unsigned* b) {
    asm volatile("mma.sync.aligned.m16n8k16.row.col.f32.bf16.bf16.f32 "
        "{%0,%1,%2,%3}, {%4,%5,%6,%7}, {%8,%9}, {%0,%1,%2,%3};"
        : "+f"(c[0]), "+f"(c[1]), "+f"(c[2]), "+f"(c[3])
        : "r"(a[0]), "r"(a[1]), "r"(a[2]), "r"(a[3]), "r"(b[0]), "r"(b[1]));
}
__device__ __forceinline__ void splitpack(float a, float b, unsigned &h, unsigned &l) {
    __nv_bfloat16 ha = __float2bfloat16(a), hb = __float2bfloat16(b);
    float la = a - __bfloat162float(ha), lb = b - __bfloat162float(hb);
    __nv_bfloat16 lA = __float2bfloat16(la), lB = __float2bfloat16(lb);
    h = (unsigned)__bfloat16_as_ushort(ha) | ((unsigned)__bfloat16_as_ushort(hb) << 16);
    l = (unsigned)__bfloat16_as_ushort(lA) | ((unsigned)__bfloat16_as_ushort(lB) << 16);
}

// ---------------------------------------------------------------------------
// Kernel 1: projections -> bf16 hi/lo splits.
// out[n][l][h] = sum_c w[h][c] * x[n][c][l] + b[h]
// ---------------------------------------------------------------------------
#define PROJ_SMEM ((256*68 + 128*260) * 4)

__global__ void __launch_bounds__(256, 1) proj_kernel(
    const float* __restrict__ x,
    const float* __restrict__ gw, const float* __restrict__ gb,
    const float* __restrict__ tw, const float* __restrict__ tb,
    const float* __restrict__ pw, const float* __restrict__ pb)
{
    extern __shared__ float sm[];
    float* xs = sm;            // [256][68]
    float* ws = sm + 256*68;   // [128][260]
    const int tid = threadIdx.x, tx = tid & 15, ty = tid >> 4;
    const int pidx = blockIdx.y, n = blockIdx.z;
    const int L0 = blockIdx.x * 64;

    const float* w = (pidx == 0) ? gw : (pidx == 1) ? tw : pw;
    const float* b = (pidx == 0) ? gb : (pidx == 1) ? tb : pb;

    const float* xg = x + (size_t)n * 256 * SEQ + L0;
    #pragma unroll
    for (int k = 0; k < 16; k++) {
        int chunk = tid + 256 * k;
        int c = chunk >> 4, l4 = chunk & 15;
        *(float4*)(xs + c*68 + l4*4) = *(const float4*)(xg + (size_t)c * SEQ + l4*4);
    }
    #pragma unroll
    for (int k = 0; k < 32; k++) {
        int chunk = tid + 256 * k;
        int h = chunk >> 6, c4 = chunk & 63;
        *(float4*)(ws + h*260 + c4*4) = *(const float4*)(w + h*256 + c4*4);
    }
    __syncthreads();

    float acc[4][8];
    #pragma unroll
    for (int i = 0; i < 4; i++)
        #pragma unroll
        for (int j = 0; j < 8; j++) acc[i][j] = 0.f;

    #pragma unroll 2
    for (int c4 = 0; c4 < 64; c4++) {
        float4 xf[4];
        #pragma unroll
        for (int cc = 0; cc < 4; cc++)
            xf[cc] = *(const float4*)(xs + (c4*4 + cc)*68 + ty*4);
        float4 wf[8];
        #pragma unroll
        for (int j = 0; j < 8; j++)
            wf[j] = *(const float4*)(ws + (tx + 16*j)*260 + c4*4);
        #pragma unroll
        for (int cc = 0; cc < 4; cc++) {
            #pragma unroll
            for (int j = 0; j < 8; j++) {
                float wv = (cc == 0) ? wf[j].x : (cc == 1) ? wf[j].y : (cc == 2) ? wf[j].z : wf[j].w;
                acc[0][j] += xf[cc].x * wv;
                acc[1][j] += xf[cc].y * wv;
                acc[2][j] += xf[cc].z * wv;
                acc[3][j] += xf[cc].w * wv;
            }
        }
    }

    float bb[8];
    #pragma unroll
    for (int j = 0; j < 8; j++) bb[j] = b[tx + 16*j];

    #pragma unroll
    for (int i = 0; i < 4; i++) {
        int l = L0 + 4*ty + i;
        #pragma unroll
        for (int j = 0; j < 8; j++) {
            int hch = tx + 16*j;
            float v = acc[i][j] + bb[j];
            __nv_bfloat16 hb = __float2bfloat16(v);
            __nv_bfloat16 lb = __float2bfloat16(v - __bfloat162float(hb));
            if (pidx == 0) {                 // g -> transposed (n, h, l)
                size_t o = ((size_t)n * 128 + hch) * SEQ + l;
                g_vh[o] = hb; g_vl[o] = lb;
            } else {
                size_t o = ((size_t)n * SEQ + l) * 128 + hch;
                if (pidx == 1) { g_qh[o] = hb; g_ql[o] = lb; }
                else           { g_kh[o] = hb; g_kl[o] = lb; }
            }
        }
    }
}

// ---------------------------------------------------------------------------
// Kernel 2: fused flash attention on mma.sync bf16 (hi/lo, 3 MMAs per product)
// CTA = 128 queries, 8 warps (16 rows each), key tiles of 64, cp.async pipeline.
// ---------------------------------------------------------------------------
#define QSTR 272          // bytes per Q/K smem row (256 data + 16 pad)
#define VSTR 144          // bytes per V^T smem row (128 data + 16 pad)
#define SM_QH 0           // 128*272 = 34816
#define SM_QL 34816
#define SM_K  69632       // 2 bufs x 34816 (hi 17408 + lo 17408)
#define SM_V  139264      // 2 bufs x 36864 (hi 18432 + lo 18432)
#define ATTN_SMEM 212992

__device__ __forceinline__ void load_kv(
    unsigned smb, int it, int tid,
    const __nv_bfloat16* Kh, const __nv_bfloat16* Kl,
    const __nv_bfloat16* Vh, const __nv_bfloat16* Vl)
{
    const int b = it & 1;
    const unsigned kb = smb + SM_K + b * 34816;
    const unsigned vb = smb + SM_V + b * 36864;
    #pragma unroll
    for (int k = 0; k < 8; k++) {                 // K: 64 rows x 128ch, hi+lo
        int c = tid + 256 * k;
        int half = c >> 10, cc = c & 1023;
        int row = cc >> 4, col16 = cc & 15;
        cp16(kb + half * 17408 + row * QSTR + col16 * 16,
             (half ? Kl : Kh) + ((size_t)(it * 64 + row)) * 128 + col16 * 8);
    }
    #pragma unroll
    for (int k = 0; k < 8; k++) {                 // V^T: 128 rows(ch) x 64 keys, hi+lo
        int c = tid + 256 * k;
        int half = c >> 10, cc = c & 1023;
        int row = cc >> 3, col16 = cc & 7;
        cp16(vb + half * 18432 + row * VSTR + col16 * 16,
             (half ? Vl : Vh) + (size_t)row * SEQ + it * 64 + col16 * 8);
    }
}

__global__ void __launch_bounds__(256, 1) attn_kernel()
{
    extern __shared__ char smc[];
    const unsigned smb = smaddr(smc);
    const int tid = threadIdx.x, wid = tid >> 5, lane = tid & 31;
    const int g = lane >> 2, t = lane & 3, r8 = lane & 7, quad = lane >> 3;
    const int n = blockIdx.y, q0 = blockIdx.x * BM;
    const int rw = wid * 16;

    const __nv_bfloat16* Qh = g_qh + (size_t)n * SEQ * 128;
    const __nv_bfloat16* Ql = g_ql + (size_t)n * SEQ * 128;
    const __nv_bfloat16* Kh = g_kh + (size_t)n * SEQ * 128;
    const __nv_bfloat16* Kl = g_kl + (size_t)n * SEQ * 128;
    const __nv_bfloat16* Vh = g_vh + (size_t)n * 128 * SEQ;
    const __nv_bfloat16* Vl = g_vl + (size_t)n * 128 * SEQ;

    // ldmatrix per-lane offsets
    // A (Q): matrices (r,k0),(r+8,k0),(r,k0+8),(r+8,k0+8)
    const unsigned qa_off = (unsigned)(rw + r8 + (quad & 1) * 8) * QSTR + (unsigned)(quad >> 1) * 16;
    // B (K/V): matrices (n0,k0),(n0,k0+8),(n0+8,k0),(n0+8,k0+8)
    const unsigned kb_off = (unsigned)(r8 + (quad >> 1) * 8) * QSTR + (unsigned)(quad & 1) * 16;
    const unsigned vb_off = (unsigned)(r8 + (quad >> 1) * 8) * VSTR + (unsigned)(quad & 1) * 16;

    // prologue: Q (hi+lo) + K/V tile 0 in one cp.async group
    #pragma unroll
    for (int k = 0; k < 16; k++) {
        int c = tid + 256 * k;
        int half = c >> 11, cc = c & 2047;
        int row = cc >> 4, col16 = cc & 15;
        cp16(smb + (half ? SM_QL : SM_QH) + row * QSTR + col16 * 16,
             (half ? Ql : Qh) + ((size_t)(q0 + row)) * 128 + col16 * 8);
    }
    load_kv(smb, 0, tid, Kh, Kl, Vh, Vl);
    CP_COMMIT();

    float o[16][4];
    #pragma unroll
    for (int i = 0; i < 16; i++)
        #pragma unroll
        for (int j = 0; j < 4; j++) o[i][j] = 0.f;
    float z0 = 0.f, z1 = 0.f, m0 = 0.f, m1 = 0.f;

    for (int it = 0; it < NKT; it++) {
        const int b = it & 1;
        if (it + 1 < NKT) {
            load_kv(smb, it + 1, tid, Kh, Kl, Vh, Vl);
            CP_COMMIT();
            CP_WAIT(1);
        } else {
            CP_WAIT(0);
        }
        __syncthreads();

        // ---- S = Q K^T : 3 passes (hh, hl, lh) fused per k-step ----
        float s[8][4];
        #pragma unroll
        for (int i = 0; i < 8; i++)
            #pragma unroll
            for (int j = 0; j < 4; j++) s[i][j] = 0.f;

        const unsigned kbh = smb + SM_K + b * 34816;
        const unsigned kbl = kbh + 17408;
        #pragma unroll
        for (int kk = 0; kk < 8; kk++) {
            unsigned Ah[4], Al[4];
            ldsm4(Ah, smb + SM_QH + qa_off + kk * 32);
            ldsm4(Al, smb + SM_QL + qa_off + kk * 32);
            #pragma unroll
            for (int np = 0; np < 4; np++) {
                unsigned Bh[4], Bl[4];
                unsigned off = kb_off + (unsigned)np * (16 * QSTR) + kk * 32;
                ldsm4(Bh, kbh + off);
                ldsm4(Bl, kbl + off);
                mma_bf16(s[2*np],   Ah, Bh);   mma_bf16(s[2*np+1], Ah, Bh + 2);
                mma_bf16(s[2*np],   Ah, Bl);   mma_bf16(s[2*np+1], Ah, Bl + 2);
                mma_bf16(s[2*np],   Al, Bh);   mma_bf16(s[2*np+1], Al, Bh + 2);
            }
        }

        // ---- softmax (shift = first-tile row max; statistically safe) ----
        if (it == 0) {
            float a0 = -1e30f, a1 = -1e30f;
            #pragma unroll
            for (int i = 0; i < 8; i++) {
                a0 = fmaxf(a0, fmaxf(s[i][0], s[i][1]));
                a1 = fmaxf(a1, fmaxf(s[i][2], s[i][3]));
            }
            a0 = fmaxf(a0, __shfl_xor_sync(0xffffffffu, a0, 1));
            a0 = fmaxf(a0, __shfl_xor_sync(0xffffffffu, a0, 2));
            a1 = fmaxf(a1, __shfl_xor_sync(0xffffffffu, a1, 1));
            a1 = fmaxf(a1, __shfl_xor_sync(0xffffffffu, a1, 2));
            m0 = a0; m1 = a1;
        }
        #pragma unroll
        for (int i = 0; i < 8; i++) {
            float p0 = __expf(s[i][0] - m0), p1 = __expf(s[i][1] - m0);
            float p2 = __expf(s[i][2] - m1), p3 = __expf(s[i][3] - m1);
            s[i][0] = p0; s[i][1] = p1; s[i][2] = p2; s[i][3] = p3;
            z0 += p0 + p1; z1 += p2 + p3;
        }

        // ---- O += P V : P stays in registers (accum frag == A frag layout) ----
        const unsigned vbh = smb + SM_V + b * 36864;
        const unsigned vbl = vbh + 18432;
        #pragma unroll
        for (int kk = 0; kk < 4; kk++) {
            unsigned Ah[4], Al[4];
            splitpack(s[2*kk][0],   s[2*kk][1],   Ah[0], Al[0]);
            splitpack(s[2*kk][2],   s[2*kk][3],   Ah[1], Al[1]);
            splitpack(s[2*kk+1][0], s[2*kk+1][1], Ah[2], Al[2]);
            splitpack(s[2*kk+1][2], s[2*kk+1][3], Ah[3], Al[3]);
            #pragma unroll
            for (int cp = 0; cp < 8; cp++) {
                unsigned Bh[4], Bl[4];
                unsigned off = vb_off + (unsigned)cp * (16 * VSTR) + kk * 32;
                ldsm4(Bh, vbh + off);
                ldsm4(Bl, vbl + off);
                mma_bf16(o[2*cp],   Ah, Bh);   mma_bf16(o[2*cp+1], Ah, Bh + 2);
                mma_bf16(o[2*cp],   Ah, Bl);   mma_bf16(o[2*cp+1], Ah, Bl + 2);
                mma_bf16(o[2*cp],   Al, Bh);   mma_bf16(o[2*cp+1], Al, Bh + 2);
            }
        }
        __syncthreads();
    }

    // ---- epilogue: normalize and store ----
    z0 += __shfl_xor_sync(0xffffffffu, z0, 1);
    z0 += __shfl_xor_sync(0xffffffffu, z0, 2);
    z1 += __shfl_xor_sync(0xffffffffu, z1, 1);
    z1 += __shfl_xor_sync(0xffffffffu, z1, 2);
    const float inv0 = 1.0f / z0, inv1 = 1.0f / z1;

    float* y0 = g_y + ((size_t)n * SEQ + q0 + rw + g) * 128;
    float* y1 = y0 + 8 * 128;
    #pragma unroll
    for (int ct = 0; ct < 16; ct++) {
        int col = 8 * ct + 2 * t;
        *(float2*)(y0 + col) = make_float2(o[ct][0] * inv0, o[ct][1] * inv0);
        *(float2*)(y1 + col) = make_float2(o[ct][2] * inv1, o[ct][3] * inv1);
    }
}

// ---------------------------------------------------------------------------
// Kernel 3: z[n][c][l] = sum_h wz[c][h] * y[n][l][h] + bz[c] + x[n][c][l]
// ---------------------------------------------------------------------------
#define OUT_SMEM ((64*132 + 256*132) * 4)

__global__ void __launch_bounds__(256, 1) out_kernel(
    const float* __restrict__ x,
    const float* __restrict__ wz, const float* __restrict__ bz,
    float* __restrict__ out)
{
    extern __shared__ float sm[];
    float* ys = sm;            // [64][132]
    float* ws = sm + 64*132;   // [256][132]
    const int tid = threadIdx.x, tx = tid & 15, ty = tid >> 4;
    const int n = blockIdx.y;
    const int L0 = blockIdx.x * 64;

    #pragma unroll
    for (int k = 0; k < 8; k++) {
        int chunk = tid + 256 * k;  int r = chunk >> 5, c4 = chunk & 31;
        *(float4*)(ys + r*132 + c4*4) =
            *(const float4*)(g_y + ((size_t)n * SEQ + L0 + r)*128 + c4*4);
    }
    #pragma unroll
    for (int k = 0; k < 32; k++) {
        int chunk = tid + 256 * k;  int c = chunk >> 5, h4 = chunk & 31;
        *(float4*)(ws + c*132 + h4*4) = *(const float4*)(wz + c*128 + h4*4);
    }
    __syncthreads();

    float acc[16][4];
    #pragma unroll
    for (int ic = 0; ic < 16; ic++)
        #pragma unroll
        for (int il = 0; il < 4; il++) acc[ic][il] = 0.f;

    for (int h4 = 0; h4 < 32; h4++) {
        float4 yf[4];
        #pragma unroll
        for (int il = 0; il < 4; il++)
            yf[il] = *(const float4*)(ys + (tx + 16*il)*132 + h4*4);
        float4 wf[16];
        #pragma unroll
        for (int ic = 0; ic < 16; ic++)
            wf[ic] = *(const float4*)(ws + (ty + 16*ic)*132 + h4*4);
        #pragma unroll
        for (int ic = 0; ic < 16; ic++)
            #pragma unroll
            for (int il = 0; il < 4; il++)
                acc[ic][il] += wf[ic].x*yf[il].x + wf[ic].y*yf[il].y
                             + wf[ic].z*yf[il].z + wf[ic].w*yf[il].w;
    }

    #pragma unroll
    for (int ic = 0; ic < 16; ic++) {
        int c = ty + 16*ic;
        float bb = bz[c];
        const float* xr = x   + ((size_t)n * 256 + c) * SEQ + L0;
        float*       zr = out + ((size_t)n * 256 + c) * SEQ + L0;
        #pragma unroll
        for (int il = 0; il < 4; il++) {
            int l = tx + 16*il;
            zr[l] = acc[ic][il] + bb + xr[l];
        }
    }
}

// ---------------------------------------------------------------------------
extern "C" void kernel_launch(void* const* d_in, const int* in_sizes, int n_in,
                              void* d_out, int out_size)
{
    (void)in_sizes; (void)n_in; (void)out_size;
    const float* x  = (const float*)d_in[0];
    const float* gw = (const float*)d_in[1];
    const float* gb = (const float*)d_in[2];
    const float* tw = (const float*)d_in[3];
    const float* tb = (const float*)d_in[4];
    const float* pw = (const float*)d_in[5];
    const float* pb = (const float*)d_in[6];
    const float* zw = (const float*)d_in[7];
    const float* zb = (const float*)d_in[8];
    float* out = (float*)d_out;

    cudaFuncSetAttribute(proj_kernel, cudaFuncAttributeMaxDynamicSharedMemorySize, PROJ_SMEM);
    cudaFuncSetAttribute(attn_kernel, cudaFuncAttributeMaxDynamicSharedMemorySize, ATTN_SMEM);
    cudaFuncSetAttribute(out_kernel,  cudaFuncAttributeMaxDynamicSharedMemorySize, OUT_SMEM);

    proj_kernel<<<dim3(QTILES, 3, 2), 256, PROJ_SMEM>>>(x, gw, gb, tw, tb, pw, pb);
    attn_kernel<<<dim3(SEQ / BM, 2),  256, ATTN_SMEM>>>();
    out_kernel <<<dim3(QTILES, 2),    256, OUT_SMEM >>>(x, zw, zb, out);
}

// round 5
// speedup vs baseline: 4.3504x; 1.3782x over previous
#include <cuda_runtime.h>
#include <cuda_bf16.h>

#define SEQ    6272
#define QTILES 98      // 64-wide L tiles for proj/out kernels
#define NKT    98      // total key tiles of 64
#define BM     128     // queries per CTA
#define KCH    3       // key chunks (split-K for wave efficiency)

// ---------------- device scratch (allocation-free) ----------------
__device__ __align__(256) __nv_bfloat16 g_qh[2*SEQ*128], g_ql[2*SEQ*128];   // theta, (n,l,h)
__device__ __align__(256) __nv_bfloat16 g_kh[2*SEQ*128], g_kl[2*SEQ*128];   // phi,   (n,l,h)
__device__ __align__(256) __nv_bfloat16 g_vh[2*128*SEQ], g_vl[2*128*SEQ];   // g, transposed (n,h,l)
__device__ __align__(256) float g_opart[2*KCH*SEQ*128];                      // partial O (unnormalized)
__device__ __align__(256) float g_zp[2*KCH*SEQ], g_mp[2*KCH*SEQ];            // partial Z, shift m

__device__ __forceinline__ unsigned smaddr(const void* p) {
    unsigned r;
    asm("{.reg .u64 t; cvta.to.shared.u64 t, %1; cvt.u32.u64 %0, t;}" : "=r"(r) : "l"(p));
    return r;
}
__device__ __forceinline__ void cp16(unsigned s, const void* g) {
    asm volatile("cp.async.cg.shared.global [%0], [%1], 16;" :: "r"(s), "l"(g) : "memory");
}
#define CP_COMMIT()  asm volatile("cp.async.commit_group;" ::: "memory")
#define CP_WAIT(N)   asm volatile("cp.async.wait_group %0;" :: "n"(N) : "memory")

__device__ __forceinline__ void ldsm4(unsigned* r, unsigned a) {
    asm volatile("ldmatrix.sync.aligned.m8n8.x4.shared.b16 {%0,%1,%2,%3}, [%4];"
        : "=r"(r[0]), "=r"(r[1]), "=r"(r[2]), "=r"(r[3]) : "r"(a));
}
__device__ __forceinline__ void mma_bf16(float* c, const unsigned* a, const unsigned* b) {
    asm volatile("mma.sync.aligned.m16n8k16.row.col.f32.bf16.bf16.f32 "
        "{%0,%1,%2,%3}, {%4,%5,%6,%7}, {%8,%9}, {%0,%1,%2,%3};"
        : "+f"(c[0]), "+f"(c[1]), "+f"(c[2]), "+f"(c[3])
        : "r"(a[0]), "r"(a[1]), "r"(a[2]), "r"(a[3]), "r"(b[0]), "r"(b[1]));
}
__device__ __forceinline__ void splitpack(float a, float b, unsigned &h, unsigned &l) {
    __nv_bfloat16 ha = __float2bfloat16(a), hb = __float2bfloat16(b);
    float la = a - __bfloat162float(ha), lb = b - __bfloat162float(hb);
    __nv_bfloat16 lA = __float2bfloat16(la), lB = __float2bfloat16(lb);
    h = (unsigned)__bfloat16_as_ushort(ha) | ((unsigned)__bfloat16_as_ushort(hb) << 16);
    l = (unsigned)__bfloat16_as_ushort(lA) | ((unsigned)__bfloat16_as_ushort(lB) << 16);
}

// ---------------------------------------------------------------------------
// Kernel 1: projections -> bf16 hi/lo splits.
// out[n][l][h] = sum_c w[h][c] * x[n][c][l] + b[h]
// V (pidx==0) is staged through smem so its (h,l)-layout store is coalesced.
// ---------------------------------------------------------------------------
#define PROJ_SMEM ((256*68 + 128*260) * 4)

__global__ void __launch_bounds__(256, 1) proj_kernel(
    const float* __restrict__ x,
    const float* __restrict__ gw, const float* __restrict__ gb,
    const float* __restrict__ tw, const float* __restrict__ tb,
    const float* __restrict__ pw, const float* __restrict__ pb)
{
    extern __shared__ float sm[];
    float* xs = sm;            // [256][68]
    float* ws = sm + 256*68;   // [128][260]
    const int tid = threadIdx.x, tx = tid & 15, ty = tid >> 4;
    const int pidx = blockIdx.y, n = blockIdx.z;
    const int L0 = blockIdx.x * 64;

    const float* w = (pidx == 0) ? gw : (pidx == 1) ? tw : pw;
    const float* b = (pidx == 0) ? gb : (pidx == 1) ? tb : pb;

    const float* xg = x + (size_t)n * 256 * SEQ + L0;
    #pragma unroll
    for (int k = 0; k < 16; k++) {
        int chunk = tid + 256 * k;
        int c = chunk >> 4, l4 = chunk & 15;
        *(float4*)(xs + c*68 + l4*4) = *(const float4*)(xg + (size_t)c * SEQ + l4*4);
    }
    #pragma unroll
    for (int k = 0; k < 32; k++) {
        int chunk = tid + 256 * k;
        int h = chunk >> 6, c4 = chunk & 63;
        *(float4*)(ws + h*260 + c4*4) = *(const float4*)(w + h*256 + c4*4);
    }
    __syncthreads();

    float acc[4][8];
    #pragma unroll
    for (int i = 0; i < 4; i++)
        #pragma unroll
        for (int j = 0; j < 8; j++) acc[i][j] = 0.f;

    #pragma unroll 2
    for (int c4 = 0; c4 < 64; c4++) {
        float4 xf[4];
        #pragma unroll
        for (int cc = 0; cc < 4; cc++)
            xf[cc] = *(const float4*)(xs + (c4*4 + cc)*68 + ty*4);
        float4 wf[8];
        #pragma unroll
        for (int j = 0; j < 8; j++)
            wf[j] = *(const float4*)(ws + (tx + 16*j)*260 + c4*4);
        #pragma unroll
        for (int cc = 0; cc < 4; cc++) {
            #pragma unroll
            for (int j = 0; j < 8; j++) {
                float wv = (cc == 0) ? wf[j].x : (cc == 1) ? wf[j].y : (cc == 2) ? wf[j].z : wf[j].w;
                acc[0][j] += xf[cc].x * wv;
                acc[1][j] += xf[cc].y * wv;
                acc[2][j] += xf[cc].z * wv;
                acc[3][j] += xf[cc].w * wv;
            }
        }
    }

    float bb[8];
    #pragma unroll
    for (int j = 0; j < 8; j++) bb[j] = b[tx + 16*j];

    if (pidx == 0) {
        // V: stage to smem as [h=128][l pitch 68], then coalesced (h,l) store
        __syncthreads();
        float* vsm = xs;
        #pragma unroll
        for (int i = 0; i < 4; i++)
            #pragma unroll
            for (int j = 0; j < 8; j++)
                vsm[(tx + 16*j)*68 + 4*ty + i] = acc[i][j] + bb[j];
        __syncthreads();
        #pragma unroll
        for (int k = 0; k < 4; k++) {
            int chunk = tid + 256 * k;          // 1024 chunks: h(128) x l8(8)
            int h = chunk >> 3, l8 = chunk & 7;
            const float* src = vsm + h*68 + l8*8;
            unsigned hw[4], lw[4];
            #pragma unroll
            for (int q2 = 0; q2 < 4; q2++)
                splitpack(src[2*q2], src[2*q2+1], hw[q2], lw[q2]);
            size_t o = ((size_t)n * 128 + h) * SEQ + L0 + l8*8;
            *(uint4*)(g_vh + o) = make_uint4(hw[0], hw[1], hw[2], hw[3]);
            *(uint4*)(g_vl + o) = make_uint4(lw[0], lw[1], lw[2], lw[3]);
        }
    } else {
        #pragma unroll
        for (int i = 0; i < 4; i++) {
            int l = L0 + 4*ty + i;
            #pragma unroll
            for (int j = 0; j < 8; j++) {
                int hch = tx + 16*j;
                float v = acc[i][j] + bb[j];
                __nv_bfloat16 hb = __float2bfloat16(v);
                __nv_bfloat16 lb = __float2bfloat16(v - __bfloat162float(hb));
                size_t o = ((size_t)n * SEQ + l) * 128 + hch;
                if (pidx == 1) { g_qh[o] = hb; g_ql[o] = lb; }
                else           { g_kh[o] = hb; g_kl[o] = lb; }
            }
        }
    }
}

// ---------------------------------------------------------------------------
// Kernel 2: fused flash attention partials on mma.sync bf16 (hi/lo, 3 MMAs).
// Grid (49, KCH, 2): each CTA = 128 queries x 1/3 of the keys; writes
// unnormalized partial O + per-row (z, m).
// ---------------------------------------------------------------------------
#define QSTR 272          // bytes per Q/K smem row (256 data + 16 pad)
#define VSTR 144          // bytes per V^T smem row (128 data + 16 pad)
#define SM_QH 0           // 128*272 = 34816
#define SM_QL 34816
#define SM_K  69632       // 2 bufs x 34816 (hi 17408 + lo 17408)
#define SM_V  139264      // 2 bufs x 36864 (hi 18432 + lo 18432)
#define ATTN_SMEM 212992

__device__ __forceinline__ void load_kv(
    unsigned smb, int jt, int buf, int tid,
    const __nv_bfloat16* Kh, const __nv_bfloat16* Kl,
    const __nv_bfloat16* Vh, const __nv_bfloat16* Vl)
{
    const unsigned kb = smb + SM_K + buf * 34816;
    const unsigned vb = smb + SM_V + buf * 36864;
    #pragma unroll
    for (int k = 0; k < 8; k++) {                 // K: 64 rows x 128ch, hi+lo
        int c = tid + 256 * k;
        int half = c >> 10, cc = c & 1023;
        int row = cc >> 4, col16 = cc & 15;
        cp16(kb + half * 17408 + row * QSTR + col16 * 16,
             (half ? Kl : Kh) + ((size_t)(jt * 64 + row)) * 128 + col16 * 8);
    }
    #pragma unroll
    for (int k = 0; k < 8; k++) {                 // V^T: 128 rows(ch) x 64 keys, hi+lo
        int c = tid + 256 * k;
        int half = c >> 10, cc = c & 1023;
        int row = cc >> 3, col16 = cc & 7;
        cp16(vb + half * 18432 + row * VSTR + col16 * 16,
             (half ? Vl : Vh) + (size_t)row * SEQ + jt * 64 + col16 * 8);
    }
}

__global__ void __launch_bounds__(256, 1) attn_kernel()
{
    extern __shared__ char smc[];
    const unsigned smb = smaddr(smc);
    const int tid = threadIdx.x, wid = tid >> 5, lane = tid & 31;
    const int g = lane >> 2, t = lane & 3, r8 = lane & 7, quad = lane >> 3;
    const int kc = blockIdx.y, n = blockIdx.z, q0 = blockIdx.x * BM;
    const int start = kc * 33;
    const int cnt = (kc == KCH - 1) ? (NKT - 33 * (KCH - 1)) : 33;
    const int rw = wid * 16;

    const __nv_bfloat16* Qh = g_qh + (size_t)n * SEQ * 128;
    const __nv_bfloat16* Ql = g_ql + (size_t)n * SEQ * 128;
    const __nv_bfloat16* Kh = g_kh + (size_t)n * SEQ * 128;
    const __nv_bfloat16* Kl = g_kl + (size_t)n * SEQ * 128;
    const __nv_bfloat16* Vh = g_vh + (size_t)n * 128 * SEQ;
    const __nv_bfloat16* Vl = g_vl + (size_t)n * 128 * SEQ;

    // ldmatrix per-lane offsets
    const unsigned qa_off = (unsigned)(rw + r8 + (quad & 1) * 8) * QSTR + (unsigned)(quad >> 1) * 16;
    const unsigned kb_off = (unsigned)(r8 + (quad >> 1) * 8) * QSTR + (unsigned)(quad & 1) * 16;
    const unsigned vb_off = (unsigned)(r8 + (quad >> 1) * 8) * VSTR + (unsigned)(quad & 1) * 16;

    // prologue: Q (hi+lo) + first K/V tile of this chunk
    #pragma unroll
    for (int k = 0; k < 16; k++) {
        int c = tid + 256 * k;
        int half = c >> 11, cc = c & 2047;
        int row = cc >> 4, col16 = cc & 15;
        cp16(smb + (half ? SM_QL : SM_QH) + row * QSTR + col16 * 16,
             (half ? Ql : Qh) + ((size_t)(q0 + row)) * 128 + col16 * 8);
    }
    load_kv(smb, start, 0, tid, Kh, Kl, Vh, Vl);
    CP_COMMIT();

    float o[16][4];
    #pragma unroll
    for (int i = 0; i < 16; i++)
        #pragma unroll
        for (int j = 0; j < 4; j++) o[i][j] = 0.f;
    float z0 = 0.f, z1 = 0.f, m0 = 0.f, m1 = 0.f;

    for (int it = 0; it < cnt; it++) {
        const int b = it & 1;
        if (it + 1 < cnt) {
            load_kv(smb, start + it + 1, b ^ 1, tid, Kh, Kl, Vh, Vl);
            CP_COMMIT();
            CP_WAIT(1);
        } else {
            CP_WAIT(0);
        }
        __syncthreads();

        // ---- S = Q K^T : 3 passes (hh, hl, lh) fused per k-step ----
        float s[8][4];
        #pragma unroll
        for (int i = 0; i < 8; i++)
            #pragma unroll
            for (int j = 0; j < 4; j++) s[i][j] = 0.f;

        const unsigned kbh = smb + SM_K + b * 34816;
        const unsigned kbl = kbh + 17408;
        #pragma unroll
        for (int kk = 0; kk < 8; kk++) {
            unsigned Ah[4], Al[4];
            ldsm4(Ah, smb + SM_QH + qa_off + kk * 32);
            ldsm4(Al, smb + SM_QL + qa_off + kk * 32);
            #pragma unroll
            for (int np = 0; np < 4; np++) {
                unsigned Bh[4], Bl[4];
                unsigned off = kb_off + (unsigned)np * (16 * QSTR) + kk * 32;
                ldsm4(Bh, kbh + off);
                ldsm4(Bl, kbl + off);
                mma_bf16(s[2*np],   Ah, Bh);   mma_bf16(s[2*np+1], Ah, Bh + 2);
                mma_bf16(s[2*np],   Ah, Bl);   mma_bf16(s[2*np+1], Ah, Bl + 2);
                mma_bf16(s[2*np],   Al, Bh);   mma_bf16(s[2*np+1], Al, Bh + 2);
            }
        }

        // ---- softmax (shift = first-tile-of-chunk row max; safe in fp32) ----
        if (it == 0) {
            float a0 = -1e30f, a1 = -1e30f;
            #pragma unroll
            for (int i = 0; i < 8; i++) {
                a0 = fmaxf(a0, fmaxf(s[i][0], s[i][1]));
                a1 = fmaxf(a1, fmaxf(s[i][2], s[i][3]));
            }
            a0 = fmaxf(a0, __shfl_xor_sync(0xffffffffu, a0, 1));
            a0 = fmaxf(a0, __shfl_xor_sync(0xffffffffu, a0, 2));
            a1 = fmaxf(a1, __shfl_xor_sync(0xffffffffu, a1, 1));
            a1 = fmaxf(a1, __shfl_xor_sync(0xffffffffu, a1, 2));
            m0 = a0; m1 = a1;
        }
        #pragma unroll
        for (int i = 0; i < 8; i++) {
            float p0 = __expf(s[i][0] - m0), p1 = __expf(s[i][1] - m0);
            float p2 = __expf(s[i][2] - m1), p3 = __expf(s[i][3] - m1);
            s[i][0] = p0; s[i][1] = p1; s[i][2] = p2; s[i][3] = p3;
            z0 += p0 + p1; z1 += p2 + p3;
        }

        // ---- O += P V : P stays in registers ----
        const unsigned vbh = smb + SM_V + b * 36864;
        const unsigned vbl = vbh + 18432;
        #pragma unroll
        for (int kk = 0; kk < 4; kk++) {
            unsigned Ah[4], Al[4];
            splitpack(s[2*kk][0],   s[2*kk][1],   Ah[0], Al[0]);
            splitpack(s[2*kk][2],   s[2*kk][3],   Ah[1], Al[1]);
            splitpack(s[2*kk+1][0], s[2*kk+1][1], Ah[2], Al[2]);
            splitpack(s[2*kk+1][2], s[2*kk+1][3], Ah[3], Al[3]);
            #pragma unroll
            for (int cp = 0; cp < 8; cp++) {
                unsigned Bh[4], Bl[4];
                unsigned off = vb_off + (unsigned)cp * (16 * VSTR) + kk * 32;
                ldsm4(Bh, vbh + off);
                ldsm4(Bl, vbl + off);
                mma_bf16(o[2*cp],   Ah, Bh);   mma_bf16(o[2*cp+1], Ah, Bh + 2);
                mma_bf16(o[2*cp],   Ah, Bl);   mma_bf16(o[2*cp+1], Ah, Bl + 2);
                mma_bf16(o[2*cp],   Al, Bh);   mma_bf16(o[2*cp+1], Al, Bh + 2);
            }
        }
        __syncthreads();
    }

    // ---- epilogue: store unnormalized partial O + (z, m) per row ----
    z0 += __shfl_xor_sync(0xffffffffu, z0, 1);
    z0 += __shfl_xor_sync(0xffffffffu, z0, 2);
    z1 += __shfl_xor_sync(0xffffffffu, z1, 1);
    z1 += __shfl_xor_sync(0xffffffffu, z1, 2);

    const size_t rbase = ((size_t)(n * KCH + kc)) * SEQ + q0 + rw + g;
    float* y0 = g_opart + rbase * 128;
    float* y1 = y0 + 8 * 128;
    #pragma unroll
    for (int ct = 0; ct < 16; ct++) {
        int col = 8 * ct + 2 * t;
        *(float2*)(y0 + col) = make_float2(o[ct][0], o[ct][1]);
        *(float2*)(y1 + col) = make_float2(o[ct][2], o[ct][3]);
    }
    if (t == 0) {
        g_zp[rbase]     = z0;  g_mp[rbase]     = m0;
        g_zp[rbase + 8] = z1;  g_mp[rbase + 8] = m1;
    }
}

// ---------------------------------------------------------------------------
// Kernel 3: combine partials + z[n][c][l] = sum_h wz[c][h]*y[n][l][h] + bz[c] + x
// ---------------------------------------------------------------------------
#define OUT_SMEM ((64*132 + 256*132 + 3*64) * 4)

__global__ void __launch_bounds__(256, 1) out_kernel(
    const float* __restrict__ x,
    const float* __restrict__ wz, const float* __restrict__ bz,
    float* __restrict__ out)
{
    extern __shared__ float sm[];
    float* ys   = sm;                    // [64][132]
    float* ws   = sm + 64*132;           // [256][132]
    float* coef = sm + 64*132 + 256*132; // [3][64]
    const int tid = threadIdx.x, tx = tid & 15, ty = tid >> 4;
    const int n = blockIdx.y;
    const int L0 = blockIdx.x * 64;

    // combine coefficients per row
    if (tid < 64) {
        int gl = L0 + tid;
        size_t b0 = (size_t)(n * KCH) * SEQ + gl;
        float m0 = g_mp[b0], m1 = g_mp[b0 + SEQ], m2 = g_mp[b0 + 2*SEQ];
        float M = fmaxf(m0, fmaxf(m1, m2));
        float w0 = __expf(m0 - M), w1 = __expf(m1 - M), w2 = __expf(m2 - M);
        float Z = g_zp[b0]*w0 + g_zp[b0 + SEQ]*w1 + g_zp[b0 + 2*SEQ]*w2;
        float iZ = 1.0f / Z;
        coef[tid] = w0*iZ; coef[64 + tid] = w1*iZ; coef[128 + tid] = w2*iZ;
    }
    __syncthreads();

    #pragma unroll
    for (int k = 0; k < 8; k++) {
        int chunk = tid + 256 * k;  int r = chunk >> 5, c4 = chunk & 31;
        size_t off = ((size_t)(n * KCH) * SEQ + L0 + r) * 128 + c4*4;
        float4 a = *(const float4*)(g_opart + off);
        float4 b = *(const float4*)(g_opart + off + (size_t)SEQ*128);
        float4 c = *(const float4*)(g_opart + off + (size_t)2*SEQ*128);
        float c0 = coef[r], c1 = coef[64 + r], c2 = coef[128 + r];
        *(float4*)(ys + r*132 + c4*4) = make_float4(
            a.x*c0 + b.x*c1 + c.x*c2,  a.y*c0 + b.y*c1 + c.y*c2,
            a.z*c0 + b.z*c1 + c.z*c2,  a.w*c0 + b.w*c1 + c.w*c2);
    }
    #pragma unroll
    for (int k = 0; k < 32; k++) {
        int chunk = tid + 256 * k;  int c = chunk >> 5, h4 = chunk & 31;
        *(float4*)(ws + c*132 + h4*4) = *(const float4*)(wz + c*128 + h4*4);
    }
    __syncthreads();

    float acc[16][4];
    #pragma unroll
    for (int ic = 0; ic < 16; ic++)
        #pragma unroll
        for (int il = 0; il < 4; il++) acc[ic][il] = 0.f;

    for (int h4 = 0; h4 < 32; h4++) {
        float4 yf[4];
        #pragma unroll
        for (int il = 0; il < 4; il++)
            yf[il] = *(const float4*)(ys + (tx + 16*il)*132 + h4*4);
        float4 wf[16];
        #pragma unroll
        for (int ic = 0; ic < 16; ic++)
            wf[ic] = *(const float4*)(ws + (ty + 16*ic)*132 + h4*4);
        #pragma unroll
        for (int ic = 0; ic < 16; ic++)
            #pragma unroll
            for (int il = 0; il < 4; il++)
                acc[ic][il] += wf[ic].x*yf[il].x + wf[ic].y*yf[il].y
                             + wf[ic].z*yf[il].z + wf[ic].w*yf[il].w;
    }

    #pragma unroll
    for (int ic = 0; ic < 16; ic++) {
        int c = ty + 16*ic;
        float bb = bz[c];
        const float* xr = x   + ((size_t)n * 256 + c) * SEQ + L0;
        float*       zr = out + ((size_t)n * 256 + c) * SEQ + L0;
        #pragma unroll
        for (int il = 0; il < 4; il++) {
            int l = tx + 16*il;
            zr[l] = acc[ic][il] + bb + xr[l];
        }
    }
}

// ---------------------------------------------------------------------------
extern "C" void kernel_launch(void* const* d_in, const int* in_sizes, int n_in,
                              void* d_out, int out_size)
{
    (void)in_sizes; (void)n_in; (void)out_size;
    const float* x  = (const float*)d_in[0];
    const float* gw = (const float*)d_in[1];
    const float* gb = (const float*)d_in[2];
    const float* tw = (const float*)d_in[3];
    const float* tb = (const float*)d_in[4];
    const float* pw = (const float*)d_in[5];
    const float* pb = (const float*)d_in[6];
    const float* zw = (const float*)d_in[7];
    const float* zb = (const float*)d_in[8];
    float* out = (float*)d_out;

    cudaFuncSetAttribute(proj_kernel, cudaFuncAttributeMaxDynamicSharedMemorySize, PROJ_SMEM);
    cudaFuncSetAttribute(attn_kernel, cudaFuncAttributeMaxDynamicSharedMemorySize, ATTN_SMEM);
    cudaFuncSetAttribute(out_kernel,  cudaFuncAttributeMaxDynamicSharedMemorySize, OUT_SMEM);

    proj_kernel<<<dim3(QTILES, 3, 2),      256, PROJ_SMEM>>>(x, gw, gb, tw, tb, pw, pb);
    attn_kernel<<<dim3(SEQ / BM, KCH, 2),  256, ATTN_SMEM>>>();
    out_kernel <<<dim3(QTILES, 2),         256, OUT_SMEM >>>(x, zw, zb, out);
}

// round 6
// speedup vs baseline: 5.0004x; 1.1494x over previous
#include <cuda_runtime.h>
#include <cuda_bf16.h>

#define SEQ    6272
#define NKT    98      // total key tiles of 64
#define BM     128     // queries per CTA
#define KCH    3       // key chunks (split-K)

// ---------------- device scratch (allocation-free) ----------------
__device__ __align__(256) __nv_bfloat16 g_xh[2*256*SEQ], g_xl[2*256*SEQ];   // x split, (n,c,l)
__device__ __align__(256) __nv_bfloat16 g_wsh[3*128*256], g_wsl[3*128*256]; // g,theta,phi weights
__device__ __align__(256) __nv_bfloat16 g_wzh[256*128],  g_wzl[256*128];    // wz
__device__ __align__(256) __nv_bfloat16 g_qh[2*SEQ*128], g_ql[2*SEQ*128];   // theta, (n,l,h)
__device__ __align__(256) __nv_bfloat16 g_kh[2*SEQ*128], g_kl[2*SEQ*128];   // phi,   (n,l,h)
__device__ __align__(256) __nv_bfloat16 g_vh[2*128*SEQ], g_vl[2*128*SEQ];   // g, transposed (n,h,l)
__device__ __align__(256) float g_opart[2*KCH*SEQ*128];                      // partial O
__device__ __align__(256) float g_zp[2*KCH*SEQ], g_mp[2*KCH*SEQ];            // partial Z, shift m

__device__ __forceinline__ unsigned smaddr(const void* p) {
    unsigned r;
    asm("{.reg .u64 t; cvta.to.shared.u64 t, %1; cvt.u32.u64 %0, t;}" : "=r"(r) : "l"(p));
    return r;
}
__device__ __forceinline__ void cp16(unsigned s, const void* g) {
    asm volatile("cp.async.cg.shared.global [%0], [%1], 16;" :: "r"(s), "l"(g) : "memory");
}
#define CP_COMMIT()  asm volatile("cp.async.commit_group;" ::: "memory")
#define CP_WAIT(N)   asm volatile("cp.async.wait_group %0;" :: "n"(N) : "memory")

__device__ __forceinline__ void ldsm4(unsigned* r, unsigned a) {
    asm volatile("ldmatrix.sync.aligned.m8n8.x4.shared.b16 {%0,%1,%2,%3}, [%4];"
        : "=r"(r[0]), "=r"(r[1]), "=r"(r[2]), "=r"(r[3]) : "r"(a));
}
__device__ __forceinline__ void ldsm4t(unsigned* r, unsigned a) {
    asm volatile("ldmatrix.sync.aligned.m8n8.x4.trans.shared.b16 {%0,%1,%2,%3}, [%4];"
        : "=r"(r[0]), "=r"(r[1]), "=r"(r[2]), "=r"(r[3]) : "r"(a));
}
__device__ __forceinline__ void mma_bf16(float* c, const unsigned* a, const unsigned* b) {
    asm volatile("mma.sync.aligned.m16n8k16.row.col.f32.bf16.bf16.f32 "
        "{%0,%1,%2,%3}, {%4,%5,%6,%7}, {%8,%9}, {%0,%1,%2,%3};"
        : "+f"(c[0]), "+f"(c[1]), "+f"(c[2]), "+f"(c[3])
        : "r"(a[0]), "r"(a[1]), "r"(a[2]), "r"(a[3]), "r"(b[0]), "r"(b[1]));
}
__device__ __forceinline__ void splitpack(float a, float b, unsigned &h, unsigned &l) {
    __nv_bfloat16 ha = __float2bfloat16(a), hb = __float2bfloat16(b);
    float la = a - __bfloat162float(ha), lb = b - __bfloat162float(hb);
    __nv_bfloat16 lA = __float2bfloat16(la), lB = __float2bfloat16(lb);
    h = (unsigned)__bfloat16_as_ushort(ha) | ((unsigned)__bfloat16_as_ushort(hb) << 16);
    l = (unsigned)__bfloat16_as_ushort(lA) | ((unsigned)__bfloat16_as_ushort(lB) << 16);
}

// ---------------------------------------------------------------------------
// Kernel 0: split x + all weights into bf16 hi/lo globals.
// blocks [0,3136): x (802816 float4).  blocks [3136,3264): weights (32768 float4).
// ---------------------------------------------------------------------------
__global__ void __launch_bounds__(256) split_kernel(
    const float* __restrict__ x,
    const float* __restrict__ gw, const float* __restrict__ tw,
    const float* __restrict__ pw, const float* __restrict__ zw)
{
    const int bid = blockIdx.x, tid = threadIdx.x;
    if (bid < 3136) {
        int i = bid * 256 + tid;                // float4 index into x
        float4 v = ((const float4*)x)[i];
        unsigned h0, l0, h1, l1;
        splitpack(v.x, v.y, h0, l0);
        splitpack(v.z, v.w, h1, l1);
        *(uint2*)(g_xh + 4*(size_t)i) = make_uint2(h0, h1);
        *(uint2*)(g_xl + 4*(size_t)i) = make_uint2(l0, l1);
    } else {
        int j = (bid - 3136) * 256 + tid;       // float4 index into weights
        int lj = j & 8191;
        const float* src;
        __nv_bfloat16 *dh, *dl;
        if (j < 8192)       { src = gw; dh = g_wsh;           dl = g_wsl; }
        else if (j < 16384) { src = tw; dh = g_wsh + 32768;   dl = g_wsl + 32768; }
        else if (j < 24576) { src = pw; dh = g_wsh + 65536;   dl = g_wsl + 65536; }
        else                { src = zw; dh = g_wzh;           dl = g_wzl; }
        float4 v = ((const float4*)src)[lj];
        unsigned h0, l0, h1, l1;
        splitpack(v.x, v.y, h0, l0);
        splitpack(v.z, v.w, h1, l1);
        *(uint2*)(dh + 4*lj) = make_uint2(h0, h1);
        *(uint2*)(dl + 4*lj) = make_uint2(l0, l1);
    }
}

// ---------------------------------------------------------------------------
// Kernel 1: projections on HMMA (bf16 hi/lo, 3 passes). K=256 in 4 chunks.
// pidx 1,2 (theta/phi): M=l(128) N=h(128), A = x^T (ldmatrix.trans), out (l,h).
// pidx 0   (g/V):       M=h(128) N=l(128), A = w,  B = x^T (trans),  out (h,l).
// ---------------------------------------------------------------------------
#define PJ_XP 272          // x chunk pitch: 128 l * 2B + 16
#define PJ_WP 144          // w chunk pitch: 64 c * 2B + 16
#define SM_PX 0            // 2 bufs x (hi 17408 + lo 17408)
#define SM_PW 69632        // 2 bufs x (hi 18432 + lo 18432)
#define PROJ_SMEM 143360

__global__ void __launch_bounds__(256, 1) proj_tc(
    const float* __restrict__ gb, const float* __restrict__ tb,
    const float* __restrict__ pb)
{
    extern __shared__ char smc[];
    const unsigned smb = smaddr(smc);
    const int tid = threadIdx.x, wid = tid >> 5, lane = tid & 31;
    const int g = lane >> 2, t = lane & 3, r8 = lane & 7, quad = lane >> 3;
    const int pidx = blockIdx.y, nn = blockIdx.z;
    const int L0 = blockIdx.x * 128;
    const int rw = wid * 16;

    const float* bias = (pidx == 0) ? gb : (pidx == 1) ? tb : pb;
    const __nv_bfloat16* Xh = g_xh + (size_t)nn * 256 * SEQ;
    const __nv_bfloat16* Xl = g_xl + (size_t)nn * 256 * SEQ;
    const __nv_bfloat16* Wh = g_wsh + pidx * 32768;
    const __nv_bfloat16* Wl = g_wsl + pidx * 32768;

    // chunk loader: c-range [64ck, 64ck+64)
    auto load_chunk = [&](int ck, int buf) {
        const unsigned xb = smb + SM_PX + buf * 34816;
        const unsigned wb = smb + SM_PW + buf * 36864;
        #pragma unroll
        for (int k = 0; k < 8; k++) {            // x: 64 c-rows x 128 l
            int c = tid + 256 * k;
            int half = c >> 10, cc = c & 1023;
            int row = cc >> 4, col8 = cc & 15;
            cp16(xb + half * 17408 + row * PJ_XP + col8 * 16,
                 (half ? Xl : Xh) + ((size_t)(ck * 64 + row)) * SEQ + L0 + col8 * 8);
        }
        #pragma unroll
        for (int k = 0; k < 8; k++) {            // w: 128 h-rows x 64 c
            int c = tid + 256 * k;
            int half = c >> 10, cc = c & 1023;
            int row = cc >> 3, col8 = cc & 7;
            cp16(wb + half * 18432 + row * PJ_WP + col8 * 16,
                 (half ? Wl : Wh) + (size_t)row * 256 + ck * 64 + col8 * 8);
        }
        CP_COMMIT();
    };

    load_chunk(0, 0);

    float s[16][4];
    #pragma unroll
    for (int i = 0; i < 16; i++)
        #pragma unroll
        for (int j = 0; j < 4; j++) s[i][j] = 0.f;

    // per-lane ldsm offsets
    // trans (x^T as A or B): row = k-part, col = m/n-part
    const unsigned xt_rowA = (unsigned)((quad >> 1) * 8 + r8);              // A-frag order
    const unsigned xt_colA = (unsigned)(rw + (quad & 1) * 8) * 2;
    const unsigned xt_rowB = (unsigned)((quad & 1) * 8 + r8);               // B-frag order
    // plain w as B (n16 blocks):
    const unsigned wB_row = (unsigned)(r8 + (quad >> 1) * 8);
    const unsigned wB_col = (unsigned)((quad & 1) * 16);
    // plain w as A (m rows = h):
    const unsigned wA_off0 = (unsigned)(rw + r8 + (quad & 1) * 8) * PJ_WP + (unsigned)((quad >> 1) * 16);

    for (int ck = 0; ck < 4; ck++) {
        const int b = ck & 1;
        if (ck + 1 < 4) { load_chunk(ck + 1, b ^ 1); CP_WAIT(1); }
        else            { CP_WAIT(0); }
        __syncthreads();

        const unsigned xh = smb + SM_PX + b * 34816, xl = xh + 17408;
        const unsigned wh = smb + SM_PW + b * 36864, wl = wh + 18432;

        if (pidx != 0) {
            // A = x^T (trans), B = w (plain)
            #pragma unroll
            for (int kk = 0; kk < 4; kk++) {
                unsigned Ah[4], Al[4];
                unsigned aoff = (kk * 16 + xt_rowA) * PJ_XP + xt_colA;
                ldsm4t(Ah, xh + aoff);
                ldsm4t(Al, xl + aoff);
                #pragma unroll
                for (int nb = 0; nb < 8; nb++) {
                    unsigned Bh[4], Bl[4];
                    unsigned boff = (nb * 16 + wB_row) * PJ_WP + kk * 32 + wB_col;
                    ldsm4(Bh, wh + boff);
                    ldsm4(Bl, wl + boff);
                    mma_bf16(s[2*nb],   Ah, Bh);  mma_bf16(s[2*nb+1], Ah, Bh + 2);
                    mma_bf16(s[2*nb],   Ah, Bl);  mma_bf16(s[2*nb+1], Ah, Bl + 2);
                    mma_bf16(s[2*nb],   Al, Bh);  mma_bf16(s[2*nb+1], Al, Bh + 2);
                }
            }
        } else {
            // A = w (plain), B = x^T (trans)
            #pragma unroll
            for (int kk = 0; kk < 4; kk++) {
                unsigned Ah[4], Al[4];
                unsigned aoff = wA_off0 + kk * 32;
                ldsm4(Ah, wh + aoff);
                ldsm4(Al, wl + aoff);
                #pragma unroll
                for (int nb = 0; nb < 8; nb++) {
                    unsigned Bh[4], Bl[4];
                    unsigned boff = (kk * 16 + xt_rowB) * PJ_XP + (nb * 16 + (quad >> 1) * 8) * 2;
                    ldsm4t(Bh, xh + boff);
                    ldsm4t(Bl, xl + boff);
                    mma_bf16(s[2*nb],   Ah, Bh);  mma_bf16(s[2*nb+1], Ah, Bh + 2);
                    mma_bf16(s[2*nb],   Ah, Bl);  mma_bf16(s[2*nb+1], Ah, Bl + 2);
                    mma_bf16(s[2*nb],   Al, Bh);  mma_bf16(s[2*nb+1], Al, Bh + 2);
                }
            }
        }
        __syncthreads();
    }

    // epilogue: add bias, splitpack, store
    if (pidx != 0) {
        __nv_bfloat16* Dh = (pidx == 1) ? g_qh : g_kh;
        __nv_bfloat16* Dl = (pidx == 1) ? g_ql : g_kl;
        const size_t l0 = (size_t)nn * SEQ + L0 + rw + g;
        #pragma unroll
        for (int j = 0; j < 16; j++) {
            int h = 8 * j + 2 * t;
            float b0 = __ldg(bias + h), b1 = __ldg(bias + h + 1);
            unsigned hw, lw;
            splitpack(s[j][0] + b0, s[j][1] + b1, hw, lw);
            *(unsigned*)(Dh + l0 * 128 + h) = hw;
            *(unsigned*)(Dl + l0 * 128 + h) = lw;
            splitpack(s[j][2] + b0, s[j][3] + b1, hw, lw);
            *(unsigned*)(Dh + (l0 + 8) * 128 + h) = hw;
            *(unsigned*)(Dl + (l0 + 8) * 128 + h) = lw;
        }
    } else {
        const int h0 = rw + g;
        float br0 = __ldg(bias + h0), br1 = __ldg(bias + h0 + 8);
        const size_t r0 = ((size_t)nn * 128 + h0) * SEQ + L0;
        #pragma unroll
        for (int j = 0; j < 16; j++) {
            int l = 8 * j + 2 * t;
            unsigned hw, lw;
            splitpack(s[j][0] + br0, s[j][1] + br0, hw, lw);
            *(unsigned*)(g_vh + r0 + l) = hw;
            *(unsigned*)(g_vl + r0 + l) = lw;
            splitpack(s[j][2] + br1, s[j][3] + br1, hw, lw);
            *(unsigned*)(g_vh + r0 + 8 * SEQ + l) = hw;
            *(unsigned*)(g_vl + r0 + 8 * SEQ + l) = lw;
        }
    }
}

// ---------------------------------------------------------------------------
// Kernel 2: fused flash attention partials (unchanged from R5).
// ---------------------------------------------------------------------------
#define QSTR 272
#define VSTR 144
#define SM_QH 0
#define SM_QL 34816
#define SM_K  69632
#define SM_V  139264
#define ATTN_SMEM 212992

__device__ __forceinline__ void load_kv(
    unsigned smb, int jt, int buf, int tid,
    const __nv_bfloat16* Kh, const __nv_bfloat16* Kl,
    const __nv_bfloat16* Vh, const __nv_bfloat16* Vl)
{
    const unsigned kb = smb + SM_K + buf * 34816;
    const unsigned vb = smb + SM_V + buf * 36864;
    #pragma unroll
    for (int k = 0; k < 8; k++) {
        int c = tid + 256 * k;
        int half = c >> 10, cc = c & 1023;
        int row = cc >> 4, col16 = cc & 15;
        cp16(kb + half * 17408 + row * QSTR + col16 * 16,
             (half ? Kl : Kh) + ((size_t)(jt * 64 + row)) * 128 + col16 * 8);
    }
    #pragma unroll
    for (int k = 0; k < 8; k++) {
        int c = tid + 256 * k;
        int half = c >> 10, cc = c & 1023;
        int row = cc >> 3, col16 = cc & 7;
        cp16(vb + half * 18432 + row * VSTR + col16 * 16,
             (half ? Vl : Vh) + (size_t)row * SEQ + jt * 64 + col16 * 8);
    }
}

__global__ void __launch_bounds__(256, 1) attn_kernel()
{
    extern __shared__ char smc[];
    const unsigned smb = smaddr(smc);
    const int tid = threadIdx.x, wid = tid >> 5, lane = tid & 31;
    const int g = lane >> 2, t = lane & 3, r8 = lane & 7, quad = lane >> 3;
    const int kc = blockIdx.y, n = blockIdx.z, q0 = blockIdx.x * BM;
    const int start = kc * 33;
    const int cnt = (kc == KCH - 1) ? (NKT - 33 * (KCH - 1)) : 33;
    const int rw = wid * 16;

    const __nv_bfloat16* Qh = g_qh + (size_t)n * SEQ * 128;
    const __nv_bfloat16* Ql = g_ql + (size_t)n * SEQ * 128;
    const __nv_bfloat16* Kh = g_kh + (size_t)n * SEQ * 128;
    const __nv_bfloat16* Kl = g_kl + (size_t)n * SEQ * 128;
    const __nv_bfloat16* Vh = g_vh + (size_t)n * 128 * SEQ;
    const __nv_bfloat16* Vl = g_vl + (size_t)n * 128 * SEQ;

    const unsigned qa_off = (unsigned)(rw + r8 + (quad & 1) * 8) * QSTR + (unsigned)(quad >> 1) * 16;
    const unsigned kb_off = (unsigned)(r8 + (quad >> 1) * 8) * QSTR + (unsigned)(quad & 1) * 16;
    const unsigned vb_off = (unsigned)(r8 + (quad >> 1) * 8) * VSTR + (unsigned)(quad & 1) * 16;

    #pragma unroll
    for (int k = 0; k < 16; k++) {
        int c = tid + 256 * k;
        int half = c >> 11, cc = c & 2047;
        int row = cc >> 4, col16 = cc & 15;
        cp16(smb + (half ? SM_QL : SM_QH) + row * QSTR + col16 * 16,
             (half ? Ql : Qh) + ((size_t)(q0 + row)) * 128 + col16 * 8);
    }
    load_kv(smb, start, 0, tid, Kh, Kl, Vh, Vl);
    CP_COMMIT();

    float o[16][4];
    #pragma unroll
    for (int i = 0; i < 16; i++)
        #pragma unroll
        for (int j = 0; j < 4; j++) o[i][j] = 0.f;
    float z0 = 0.f, z1 = 0.f, m0 = 0.f, m1 = 0.f;

    for (int it = 0; it < cnt; it++) {
        const int b = it & 1;
        if (it + 1 < cnt) {
            load_kv(smb, start + it + 1, b ^ 1, tid, Kh, Kl, Vh, Vl);
            CP_COMMIT();
            CP_WAIT(1);
        } else {
            CP_WAIT(0);
        }
        __syncthreads();

        float s[8][4];
        #pragma unroll
        for (int i = 0; i < 8; i++)
            #pragma unroll
            for (int j = 0; j < 4; j++) s[i][j] = 0.f;

        const unsigned kbh = smb + SM_K + b * 34816;
        const unsigned kbl = kbh + 17408;
        #pragma unroll
        for (int kk = 0; kk < 8; kk++) {
            unsigned Ah[4], Al[4];
            ldsm4(Ah, smb + SM_QH + qa_off + kk * 32);
            ldsm4(Al, smb + SM_QL + qa_off + kk * 32);
            #pragma unroll
            for (int np = 0; np < 4; np++) {
                unsigned Bh[4], Bl[4];
                unsigned off = kb_off + (unsigned)np * (16 * QSTR) + kk * 32;
                ldsm4(Bh, kbh + off);
                ldsm4(Bl, kbl + off);
                mma_bf16(s[2*np],   Ah, Bh);   mma_bf16(s[2*np+1], Ah, Bh + 2);
                mma_bf16(s[2*np],   Ah, Bl);   mma_bf16(s[2*np+1], Ah, Bl + 2);
                mma_bf16(s[2*np],   Al, Bh);   mma_bf16(s[2*np+1], Al, Bh + 2);
            }
        }

        if (it == 0) {
            float a0 = -1e30f, a1 = -1e30f;
            #pragma unroll
            for (int i = 0; i < 8; i++) {
                a0 = fmaxf(a0, fmaxf(s[i][0], s[i][1]));
                a1 = fmaxf(a1, fmaxf(s[i][2], s[i][3]));
            }
            a0 = fmaxf(a0, __shfl_xor_sync(0xffffffffu, a0, 1));
            a0 = fmaxf(a0, __shfl_xor_sync(0xffffffffu, a0, 2));
            a1 = fmaxf(a1, __shfl_xor_sync(0xffffffffu, a1, 1));
            a1 = fmaxf(a1, __shfl_xor_sync(0xffffffffu, a1, 2));
            m0 = a0; m1 = a1;
        }
        #pragma unroll
        for (int i = 0; i < 8; i++) {
            float p0 = __expf(s[i][0] - m0), p1 = __expf(s[i][1] - m0);
            float p2 = __expf(s[i][2] - m1), p3 = __expf(s[i][3] - m1);
            s[i][0] = p0; s[i][1] = p1; s[i][2] = p2; s[i][3] = p3;
            z0 += p0 + p1; z1 += p2 + p3;
        }

        const unsigned vbh = smb + SM_V + b * 36864;
        const unsigned vbl = vbh + 18432;
        #pragma unroll
        for (int kk = 0; kk < 4; kk++) {
            unsigned Ah[4], Al[4];
            splitpack(s[2*kk][0],   s[2*kk][1],   Ah[0], Al[0]);
            splitpack(s[2*kk][2],   s[2*kk][3],   Ah[1], Al[1]);
            splitpack(s[2*kk+1][0], s[2*kk+1][1], Ah[2], Al[2]);
            splitpack(s[2*kk+1][2], s[2*kk+1][3], Ah[3], Al[3]);
            #pragma unroll
            for (int cp = 0; cp < 8; cp++) {
                unsigned Bh[4], Bl[4];
                unsigned off = vb_off + (unsigned)cp * (16 * VSTR) + kk * 32;
                ldsm4(Bh, vbh + off);
                ldsm4(Bl, vbl + off);
                mma_bf16(o[2*cp],   Ah, Bh);   mma_bf16(o[2*cp+1], Ah, Bh + 2);
                mma_bf16(o[2*cp],   Ah, Bl);   mma_bf16(o[2*cp+1], Ah, Bl + 2);
                mma_bf16(o[2*cp],   Al, Bh);   mma_bf16(o[2*cp+1], Al, Bh + 2);
            }
        }
        __syncthreads();
    }

    z0 += __shfl_xor_sync(0xffffffffu, z0, 1);
    z0 += __shfl_xor_sync(0xffffffffu, z0, 2);
    z1 += __shfl_xor_sync(0xffffffffu, z1, 1);
    z1 += __shfl_xor_sync(0xffffffffu, z1, 2);

    const size_t rbase = ((size_t)(n * KCH + kc)) * SEQ + q0 + rw + g;
    float* y0 = g_opart + rbase * 128;
    float* y1 = y0 + 8 * 128;
    #pragma unroll
    for (int ct = 0; ct < 16; ct++) {
        int col = 8 * ct + 2 * t;
        *(float2*)(y0 + col) = make_float2(o[ct][0], o[ct][1]);
        *(float2*)(y1 + col) = make_float2(o[ct][2], o[ct][3]);
    }
    if (t == 0) {
        g_zp[rbase]     = z0;  g_mp[rbase]     = m0;
        g_zp[rbase + 8] = z1;  g_mp[rbase + 8] = m1;
    }
}

// ---------------------------------------------------------------------------
// Kernel 3: combine partials -> y bf16 hi/lo in smem -> HMMA with wz -> +bias+x.
// CTA: 256 c x 64 l.  M=256(c) N=64(l) K=128(h), 3-pass.
// ---------------------------------------------------------------------------
#define OT_P 272
#define SM_WZH 0               // 256*272 = 69632
#define SM_WZL 69632
#define SM_YH  139264          // 64*272 = 17408
#define SM_YL  156672
#define SM_CF  174080          // 192 floats
#define OUT_SMEM 174848

__global__ void __launch_bounds__(256, 1) out_tc(
    const float* __restrict__ x, const float* __restrict__ bz,
    float* __restrict__ out)
{
    extern __shared__ char smc[];
    const unsigned smb = smaddr(smc);
    float* coef = (float*)(smc + SM_CF);
    const int tid = threadIdx.x, wid = tid >> 5, lane = tid & 31;
    const int g = lane >> 2, t = lane & 3, r8 = lane & 7, quad = lane >> 3;
    const int n = blockIdx.y;
    const int L0 = blockIdx.x * 64;

    // 1. wz hi/lo via cp.async (8192 cp16)
    #pragma unroll
    for (int k = 0; k < 32; k++) {
        int c = tid + 256 * k;
        int half = c >> 12, cc = c & 4095;
        int row = cc >> 4, col8 = cc & 15;
        cp16(smb + (half ? SM_WZL : SM_WZH) + row * OT_P + col8 * 16,
             (half ? g_wzl : g_wzh) + (size_t)row * 128 + col8 * 8);
    }
    CP_COMMIT();

    // 2. combine coefficients
    if (tid < 64) {
        size_t b0 = (size_t)(n * KCH) * SEQ + L0 + tid;
        float m0 = g_mp[b0], m1 = g_mp[b0 + SEQ], m2 = g_mp[b0 + 2*SEQ];
        float M = fmaxf(m0, fmaxf(m1, m2));
        float w0 = __expf(m0 - M), w1 = __expf(m1 - M), w2 = __expf(m2 - M);
        float Z = g_zp[b0]*w0 + g_zp[b0 + SEQ]*w1 + g_zp[b0 + 2*SEQ]*w2;
        float iZ = 1.0f / Z;
        coef[tid] = w0*iZ; coef[64 + tid] = w1*iZ; coef[128 + tid] = w2*iZ;
    }
    __syncthreads();

    // 3. combine partial O -> y bf16 hi/lo in smem (64 l x 128 h)
    #pragma unroll
    for (int k = 0; k < 8; k++) {
        int idx = tid + 256 * k;
        int r = idx >> 5, c4 = idx & 31;
        size_t off = ((size_t)(n * KCH) * SEQ + L0 + r) * 128 + c4 * 4;
        float4 a = *(const float4*)(g_opart + off);
        float4 b = *(const float4*)(g_opart + off + (size_t)SEQ*128);
        float4 c = *(const float4*)(g_opart + off + (size_t)2*SEQ*128);
        float c0 = coef[r], c1 = coef[64 + r], c2 = coef[128 + r];
        float y0 = a.x*c0 + b.x*c1 + c.x*c2, y1 = a.y*c0 + b.y*c1 + c.y*c2;
        float y2 = a.z*c0 + b.z*c1 + c.z*c2, y3 = a.w*c0 + b.w*c1 + c.w*c2;
        unsigned h0, l0, h1, l1;
        splitpack(y0, y1, h0, l0);
        splitpack(y2, y3, h1, l1);
        *(uint2*)(smc + SM_YH + r * OT_P + c4 * 8) = make_uint2(h0, h1);
        *(uint2*)(smc + SM_YL + r * OT_P + c4 * 8) = make_uint2(l0, l1);
    }
    CP_WAIT(0);
    __syncthreads();

    // 4. MMA: A = wz (plain), B = y (plain)
    float acc[2][8][4];
    #pragma unroll
    for (int mb = 0; mb < 2; mb++)
        #pragma unroll
        for (int j = 0; j < 8; j++)
            #pragma unroll
            for (int q = 0; q < 4; q++) acc[mb][j][q] = 0.f;

    const unsigned aoff0 = (unsigned)(wid * 32 + r8 + (quad & 1) * 8) * OT_P + (unsigned)((quad >> 1) * 16);
    const unsigned boff0 = (unsigned)(r8 + (quad >> 1) * 8) * OT_P + (unsigned)((quad & 1) * 16);

    #pragma unroll
    for (int kk = 0; kk < 8; kk++) {
        unsigned Ah[2][4], Al[2][4];
        #pragma unroll
        for (int mb = 0; mb < 2; mb++) {
            unsigned ao = aoff0 + (unsigned)(mb * 16) * OT_P + kk * 32;
            ldsm4(Ah[mb], smb + SM_WZH + ao);
            ldsm4(Al[mb], smb + SM_WZL + ao);
        }
        #pragma unroll
        for (int nb = 0; nb < 4; nb++) {
            unsigned Bh[4], Bl[4];
            unsigned bo = boff0 + (unsigned)(nb * 16) * OT_P + kk * 32;
            ldsm4(Bh, smb + SM_YH + bo);
            ldsm4(Bl, smb + SM_YL + bo);
            #pragma unroll
            for (int mb = 0; mb < 2; mb++) {
                mma_bf16(acc[mb][2*nb],   Ah[mb], Bh);  mma_bf16(acc[mb][2*nb+1], Ah[mb], Bh + 2);
                mma_bf16(acc[mb][2*nb],   Ah[mb], Bl);  mma_bf16(acc[mb][2*nb+1], Ah[mb], Bl + 2);
                mma_bf16(acc[mb][2*nb],   Al[mb], Bh);  mma_bf16(acc[mb][2*nb+1], Al[mb], Bh + 2);
            }
        }
    }

    // 5. epilogue: + bias + residual, store
    #pragma unroll
    for (int mb = 0; mb < 2; mb++) {
        int c0 = wid * 32 + mb * 16 + g;
        int c1 = c0 + 8;
        float b0 = __ldg(bz + c0), b1 = __ldg(bz + c1);
        const float* xr0 = x   + ((size_t)n * 256 + c0) * SEQ + L0;
        const float* xr1 = x   + ((size_t)n * 256 + c1) * SEQ + L0;
        float*       zr0 = out + ((size_t)n * 256 + c0) * SEQ + L0;
        float*       zr1 = out + ((size_t)n * 256 + c1) * SEQ + L0;
        #pragma unroll
        for (int j = 0; j < 8; j++) {
            int l = 8 * j + 2 * t;
            float2 xa = *(const float2*)(xr0 + l);
            float2 xb = *(const float2*)(xr1 + l);
            *(float2*)(zr0 + l) = make_float2(acc[mb][j][0] + b0 + xa.x, acc[mb][j][1] + b0 + xa.y);
            *(float2*)(zr1 + l) = make_float2(acc[mb][j][2] + b1 + xb.x, acc[mb][j][3] + b1 + xb.y);
        }
    }
}

// ---------------------------------------------------------------------------
extern "C" void kernel_launch(void* const* d_in, const int* in_sizes, int n_in,
                              void* d_out, int out_size)
{
    (void)in_sizes; (void)n_in; (void)out_size;
    const float* x  = (const float*)d_in[0];
    const float* gw = (const float*)d_in[1];
    const float* gb = (const float*)d_in[2];
    const float* tw = (const float*)d_in[3];
    const float* tb = (const float*)d_in[4];
    const float* pw = (const float*)d_in[5];
    const float* pb = (const float*)d_in[6];
    const float* zw = (const float*)d_in[7];
    const float* zb = (const float*)d_in[8];
    float* out = (float*)d_out;

    cudaFuncSetAttribute(proj_tc,     cudaFuncAttributeMaxDynamicSharedMemorySize, PROJ_SMEM);
    cudaFuncSetAttribute(attn_kernel, cudaFuncAttributeMaxDynamicSharedMemorySize, ATTN_SMEM);
    cudaFuncSetAttribute(out_tc,      cudaFuncAttributeMaxDynamicSharedMemorySize, OUT_SMEM);

    split_kernel<<<3264, 256>>>(x, gw, tw, pw, zw);
    proj_tc<<<dim3(49, 3, 2),     256, PROJ_SMEM>>>(gb, tb, pb);
    attn_kernel<<<dim3(49, KCH, 2), 256, ATTN_SMEM>>>();
    out_tc<<<dim3(98, 2),         256, OUT_SMEM>>>(x, zb, out);
}